// round 11
// baseline (speedup 1.0000x reference)
#include <cuda_runtime.h>
#include <math.h>

#define BB 4
#define NN 4096
#define CC 256
#define NQ 14
#define DK 512
#define NM 15

// ---------------- scratch (device globals; allocation-free) ----------------
__device__ float g_qs[BB*NN*CC];
__device__ float g_kk[BB*NN*CC];
__device__ float g_vv[BB*NN*CC];
__device__ float g_kh[BB*NN*DK];
__device__ float g_vh[BB*NN*DK];
__device__ float g_seed[BB*NQ*CC];
__device__ float g_qh[BB*NQ*DK];
__device__ float g_logits[BB*NQ*NN];
__device__ float g_ctx[BB*NQ*DK];
__device__ float g_pkn[BB*NQ*CC];
__device__ float g_pqn[BB*NQ*CC];
__device__ float g_q2p[BB*NN*NQ];
__device__ int   g_sidq[BB*NN];
__device__ float g_Kmat[BB*NN*NM];
__device__ float g_s2p[BB*NN*NQ];
__device__ int   g_sids[BB*NN];
__device__ float g_rowm[BB*NM];
__device__ float g_Ptab[NQ*NQ];
__device__ float g_part[2*8*NM];
__device__ int   g_ctr;
__device__ float g_xattn[BB*NN*CC];

__device__ __forceinline__ float d4(float4 a, float4 b) {
    return a.x*b.x + a.y*b.y + a.z*b.z + a.w*b.w;
}
__device__ __forceinline__ float wsum(float v) {
    #pragma unroll
    for (int o = 16; o; o >>= 1) v += __shfl_xor_sync(0xffffffffu, v, o);
    return v;
}
__device__ __forceinline__ float wmax(float v) {
    #pragma unroll
    for (int o = 16; o; o >>= 1) v = fmaxf(v, __shfl_xor_sync(0xffffffffu, v, o));
    return v;
}

// ---------------------------------------------------------------------------
// GEMM, K=256: Y[16384, NC] = X[16384,256] @ W[256,NC].  128x128 tile, 8x8 micro.
// ---------------------------------------------------------------------------
__global__ __launch_bounds__(256) void gemm_k256(const float* __restrict__ X,
                                                 const float* __restrict__ W,
                                                 float* __restrict__ Y, int NC)
{
    __shared__ __align__(16) float Xs[16][128];
    __shared__ __align__(16) float Bs[16][128];
    const int t  = threadIdx.x;
    const int m0 = blockIdx.y * 128;
    const int n0 = blockIdx.x * 128;
    const int tx = t & 15, ty = t >> 4;

    float acc[8][8];
    #pragma unroll
    for (int i = 0; i < 8; i++)
        #pragma unroll
        for (int j = 0; j < 8; j++) acc[i][j] = 0.f;

    for (int kt = 0; kt < 256; kt += 16) {
        __syncthreads();
        #pragma unroll
        for (int h = 0; h < 2; h++) {
            int f4  = t + 256 * h;
            int row = f4 >> 2, kq = f4 & 3;
            float4 xv = *(const float4*)(X + (size_t)(m0 + row) * 256 + kt + kq * 4);
            Xs[kq*4+0][row] = xv.x; Xs[kq*4+1][row] = xv.y;
            Xs[kq*4+2][row] = xv.z; Xs[kq*4+3][row] = xv.w;
            int r = f4 >> 5, c4 = f4 & 31;
            *(float4*)&Bs[r][c4*4] = *(const float4*)(W + (size_t)(kt + r) * NC + n0 + c4 * 4);
        }
        __syncthreads();
        #pragma unroll
        for (int kk2 = 0; kk2 < 16; kk2++) {
            float4 a0 = *(float4*)&Xs[kk2][ty*8];
            float4 a1 = *(float4*)&Xs[kk2][ty*8+4];
            float4 b0 = *(float4*)&Bs[kk2][tx*8];
            float4 b1 = *(float4*)&Bs[kk2][tx*8+4];
            float av[8] = {a0.x,a0.y,a0.z,a0.w,a1.x,a1.y,a1.z,a1.w};
            float bv[8] = {b0.x,b0.y,b0.z,b0.w,b1.x,b1.y,b1.z,b1.w};
            #pragma unroll
            for (int i = 0; i < 8; i++)
                #pragma unroll
                for (int j = 0; j < 8; j++) acc[i][j] += av[i] * bv[j];
        }
    }
    #pragma unroll
    for (int i = 0; i < 8; i++) {
        float* yr = Y + (size_t)(m0 + ty*8 + i) * NC + n0 + tx*8;
        *(float4*)yr       = make_float4(acc[i][0], acc[i][1], acc[i][2], acc[i][3]);
        *(float4*)(yr + 4) = make_float4(acc[i][4], acc[i][5], acc[i][6], acc[i][7]);
    }
}

// ---------------------------------------------------------------------------
// Prep: alignment table, row marginals, barrier counter reset
// ---------------------------------------------------------------------------
__global__ __launch_bounds__(256) void prep_kernel(const int* __restrict__ supp_mask)
{
    int t = threadIdx.x;
    if (t == 0) g_ctr = 0;
    if (t < NQ*NQ) {
        int s = t / NQ, q = t % NQ;
        int prod = (2*s + 3) * (2*q + 3);
        int r = (int)(sqrtf((float)prod) + 0.5f);
        g_Ptab[t] = (r*r == prod) ? 0.f : -10000.f;
    }
    __shared__ int red[256];
    int b = t >> 6, j = t & 63;
    int cnt = 0;
    for (int i = j; i < NN; i += 64) cnt += (supp_mask[b*NN + i] == 0);
    red[t] = cnt;
    __syncthreads();
    for (int o = 32; o; o >>= 1) { if (j < o) red[t] += red[t + o]; __syncthreads(); }
    if (j == 0) {
        float nbg = (float)red[t];
        float nfg = (float)NN - nbg;
        for (int m2 = 0; m2 < NQ; m2++) g_rowm[b*NM + m2] = nfg / (float)(NQ * NN);
        g_rowm[b*NM + NQ] = nbg / (float)NN;
    }
}

// ---------------------------------------------------------------------------
// seed[b,q,d] = sum_c sv[b,c,q]*Ws[c,d];  qh = seed @ Wqs
// ---------------------------------------------------------------------------
__global__ __launch_bounds__(256) void seed_qh_kernel(const float* __restrict__ sv,
                                                      const float* __restrict__ Ws,
                                                      const float* __restrict__ Wqs)
{
    __shared__ float svc[CC];
    __shared__ float sd[CC];
    int bq = blockIdx.x;
    int b = bq / NQ, q = bq % NQ;
    int t = threadIdx.x;
    svc[t] = sv[((size_t)b*CC + t)*NQ + q];
    __syncthreads();
    float a = 0.f;
    #pragma unroll 8
    for (int c = 0; c < CC; c++) a += svc[c] * Ws[(size_t)c*CC + t];
    g_seed[(size_t)bq*CC + t] = a;
    sd[t] = a;
    __syncthreads();
    #pragma unroll
    for (int h = 0; h < 2; h++) {
        int d = t + 256*h;
        float a2 = 0.f;
        #pragma unroll 8
        for (int c = 0; c < CC; c++) a2 += sd[c] * Wqs[(size_t)c*DK + d];
        g_qh[(size_t)bq*DK + d] = a2;
    }
}

// ---------------------------------------------------------------------------
// logits[b,q,n] = qh.kh/sqrt(512), masked -1e9 where supp_mask==0
// ---------------------------------------------------------------------------
__global__ __launch_bounds__(256) void logits_kernel(const int* __restrict__ supp_mask)
{
    __shared__ __align__(16) float qh_s[NQ*DK];
    int b = blockIdx.y;
    int n = blockIdx.x * 256 + threadIdx.x;
    for (int i = threadIdx.x; i < NQ*DK; i += 256) qh_s[i] = g_qh[(size_t)b*NQ*DK + i];
    __syncthreads();
    const float4* kh4 = (const float4*)(g_kh + ((size_t)b*NN + n) * DK);
    float acc[NQ];
    #pragma unroll
    for (int q = 0; q < NQ; q++) acc[q] = 0.f;
    for (int c4 = 0; c4 < DK/4; c4++) {
        float4 kv = kh4[c4];
        #pragma unroll
        for (int q = 0; q < NQ; q++) {
            float4 qv = *(float4*)&qh_s[q*DK + c4*4];
            acc[q] += d4(kv, qv);
        }
    }
    const float sc = 0.044194173824159216f;  // 1/sqrt(512)
    bool masked = (supp_mask[b*NN + n] == 0);
    #pragma unroll
    for (int q = 0; q < NQ; q++)
        g_logits[((size_t)b*NQ + q)*NN + n] = masked ? -1e9f : acc[q] * sc;
}

// ---------------------------------------------------------------------------
// A = softmax(logits); ctx[b,q,d] = sum_n A[n]*vh[b,n,d]   (one block per (q,b))
// ---------------------------------------------------------------------------
__global__ __launch_bounds__(512) void softmax_ctx_kernel()
{
    __shared__ float ls[NN];
    __shared__ float red[512];
    int q = blockIdx.x, b = blockIdx.y, t = threadIdx.x;
    const float* lrow = g_logits + ((size_t)b*NQ + q) * NN;
    float lmax = -INFINITY;
    for (int i = t; i < NN; i += 512) { float v = lrow[i]; ls[i] = v; lmax = fmaxf(lmax, v); }
    red[t] = lmax;
    __syncthreads();
    for (int o = 256; o; o >>= 1) { if (t < o) red[t] = fmaxf(red[t], red[t+o]); __syncthreads(); }
    float m = red[0];
    __syncthreads();
    float lsum = 0.f;
    for (int i = t; i < NN; i += 512) { float p = expf(ls[i] - m); ls[i] = p; lsum += p; }
    red[t] = lsum;
    __syncthreads();
    for (int o = 256; o; o >>= 1) { if (t < o) red[t] += red[t+o]; __syncthreads(); }
    float S = red[0];
    __syncthreads();
    const float* vb = g_vh + (size_t)b*NN*DK;
    float a0 = 0.f, a1 = 0.f, a2 = 0.f, a3 = 0.f;
    for (int n = 0; n < NN; n += 4) {
        a0 += ls[n+0] * vb[(size_t)(n+0)*DK + t];
        a1 += ls[n+1] * vb[(size_t)(n+1)*DK + t];
        a2 += ls[n+2] * vb[(size_t)(n+2)*DK + t];
        a3 += ls[n+3] * vb[(size_t)(n+3)*DK + t];
    }
    g_ctx[((size_t)b*NQ + q)*DK + t] = ((a0 + a1) + (a2 + a3)) / S;
}

// ---------------------------------------------------------------------------
// prototypes = LN(ctx@Wfc + bfc + seed); pk=prot@Wsk, pq=prot@Wsq, l2-normalized
// ---------------------------------------------------------------------------
__global__ __launch_bounds__(256) void proto_kernel(const float* __restrict__ Wfc,
    const float* __restrict__ bfc, const float* __restrict__ ln_g,
    const float* __restrict__ ln_b, const float* __restrict__ Wsk,
    const float* __restrict__ Wsq)
{
    __shared__ float cs[DK];
    __shared__ float ps[CC];
    __shared__ float red[256];
    int bq = blockIdx.x, t = threadIdx.x;
    cs[t]       = g_ctx[(size_t)bq*DK + t];
    cs[t + 256] = g_ctx[(size_t)bq*DK + t + 256];
    __syncthreads();
    float pre = bfc[t] + g_seed[(size_t)bq*CC + t];
    #pragma unroll 8
    for (int k2 = 0; k2 < DK; k2++) pre += cs[k2] * Wfc[(size_t)k2*CC + t];
    red[t] = pre;
    __syncthreads();
    for (int o = 128; o; o >>= 1) { if (t < o) red[t] += red[t+o]; __syncthreads(); }
    float mu = red[0] * (1.f/256.f);
    __syncthreads();
    float dd = pre - mu;
    red[t] = dd * dd;
    __syncthreads();
    for (int o = 128; o; o >>= 1) { if (t < o) red[t] += red[t+o]; __syncthreads(); }
    float var = red[0] * (1.f/256.f);
    __syncthreads();
    float prot = dd / sqrtf(var + 1e-5f) * ln_g[t] + ln_b[t];
    ps[t] = prot;
    __syncthreads();
    float pk = 0.f, pq = 0.f;
    #pragma unroll 8
    for (int c = 0; c < CC; c++) {
        float pv = ps[c];
        pk += pv * Wsk[(size_t)c*CC + t];
        pq += pv * Wsq[(size_t)c*CC + t];
    }
    red[t] = pk * pk;
    __syncthreads();
    for (int o = 128; o; o >>= 1) { if (t < o) red[t] += red[t+o]; __syncthreads(); }
    float nk = sqrtf(red[0]);
    __syncthreads();
    red[t] = pq * pq;
    __syncthreads();
    for (int o = 128; o; o >>= 1) { if (t < o) red[t] += red[t+o]; __syncthreads(); }
    float nq2 = sqrtf(red[0]);
    g_pkn[(size_t)bq*CC + t] = pk / fmaxf(nk,  1e-12f);
    g_pqn[(size_t)bq*CC + t] = pq / fmaxf(nq2, 1e-12f);
}

// ---------------------------------------------------------------------------
// Per-row: q2p (+argmax), Kmat = exp(-cost/0.05). One warp per row.
// ---------------------------------------------------------------------------
__global__ __launch_bounds__(256) void rowsim_kernel(const int* __restrict__ supp_mask)
{
    __shared__ __align__(16) float pkn_s[NQ*CC];
    __shared__ __align__(16) float pqn_s[NQ*CC];
    int t = threadIdx.x, lane = t & 31, wid = t >> 5;
    int g = blockIdx.x * 8 + wid;
    int b = g >> 12;
    for (int i = t; i < NQ*CC; i += 256) {
        pkn_s[i] = g_pkn[(size_t)b*NQ*CC + i];
        pqn_s[i] = g_pqn[(size_t)b*NQ*CC + i];
    }
    __syncthreads();
    const float* qrow = g_qs + (size_t)g*CC;
    const float* krow = g_kk + (size_t)g*CC;
    float4 q0 = *(const float4*)(qrow + lane*4);
    float4 q1 = *(const float4*)(qrow + 128 + lane*4);
    float4 k0 = *(const float4*)(krow + lane*4);
    float4 k1 = *(const float4*)(krow + 128 + lane*4);
    float rnq = 1.f / fmaxf(sqrtf(wsum(d4(q0,q0) + d4(q1,q1))), 1e-12f);
    float rnk = 1.f / fmaxf(sqrtf(wsum(d4(k0,k0) + d4(k1,k1))), 1e-12f);
    float myq2p = 0.f, myK = 0.f;
    float best = -INFINITY; int bk = 0;
    #pragma unroll
    for (int k2 = 0; k2 < NQ; k2++) {
        float4 p0 = *(float4*)&pkn_s[k2*CC + lane*4];
        float4 p1 = *(float4*)&pkn_s[k2*CC + 128 + lane*4];
        float val = wsum(d4(q0,p0) + d4(q1,p1)) * rnq;
        if (val > best) { best = val; bk = k2; }
        if (lane == k2) myq2p = val;
        float4 r0 = *(float4*)&pqn_s[k2*CC + lane*4];
        float4 r1 = *(float4*)&pqn_s[k2*CC + 128 + lane*4];
        float a = wsum(d4(k0,r0) + d4(k1,r1)) * rnk;
        if (lane == k2) myK = expf(20.f * (a - 1.f));   // exp(-(1-att)/0.05)
    }
    if (lane < NQ) {
        g_q2p[(size_t)g*NQ + lane]  = myq2p;
        g_Kmat[(size_t)g*NM + lane] = myK;
    }
    if (lane == NQ)
        g_Kmat[(size_t)g*NM + NQ] = (supp_mask[g] > 0) ? expf(-40.f) : 1.f;
    if (lane == 0) g_sidq[g] = bk;
}

// ---------------------------------------------------------------------------
// Sinkhorn: 8 blocks (2 per batch), K in registers, 100 iterations with a
// parity-buffered global-counter barrier. Fixed-order sums -> deterministic.
// ---------------------------------------------------------------------------
__global__ __launch_bounds__(512) void sinkhorn_kernel()
{
    __shared__ float sred[16*NM];
    __shared__ float v_s[NM];
    int t = threadIdx.x, lane = t & 31, wid = t >> 5;
    int b = blockIdx.x >> 1, half = blockIdx.x & 1;

    float Kl[4][NM];
    int rowg[4];
    #pragma unroll
    for (int i = 0; i < 4; i++) {
        int n = half*2048 + i*512 + t;
        rowg[i] = b*NN + n;
        #pragma unroll
        for (int j = 0; j < NM; j++) Kl[i][j] = g_Kmat[(size_t)rowg[i]*NM + j];
    }
    float u[4] = {1.f/NN, 1.f/NN, 1.f/NN, 1.f/NN};

    for (int iter = 0; iter < 100; iter++) {
        #pragma unroll
        for (int j = 0; j < NM; j++) {
            float x = Kl[0][j]*u[0] + Kl[1][j]*u[1] + Kl[2][j]*u[2] + Kl[3][j]*u[3];
            x = wsum(x);
            if (lane == 0) sred[wid*NM + j] = x;
        }
        __syncthreads();
        if (t < NM) {
            float bp = 0.f;
            for (int w = 0; w < 16; w++) bp += sred[w*NM + t];
            g_part[((iter & 1)*8 + blockIdx.x)*NM + t] = bp;
            __threadfence();
        }
        __syncthreads();
        if (t == 0) {
            atomicAdd(&g_ctr, 1);
            while (atomicAdd(&g_ctr, 0) < 8*(iter + 1)) { }
            __threadfence();
        }
        __syncthreads();
        if (t < NM) {
            volatile float* vp = (volatile float*)g_part;
            int base = ((iter & 1)*8 + b*2)*NM;
            float tot = vp[base + t] + vp[base + NM + t];
            v_s[t] = g_rowm[b*NM + t] / (tot + 1e-16f);
        }
        __syncthreads();
        #pragma unroll
        for (int i = 0; i < 4; i++) {
            float dsum = 0.f;
            #pragma unroll
            for (int j = 0; j < NM; j++) dsum += Kl[i][j]*v_s[j];
            u[i] = (1.f/NN) / (dsum + 1e-16f);
        }
    }
    #pragma unroll
    for (int i = 0; i < 4; i++) {
        float best = -INFINITY; int bk = 0;
        #pragma unroll
        for (int j = 0; j < NQ; j++) {
            float tv = fmaxf(u[i]*Kl[i][j]*v_s[j]*(float)NN, 0.f);
            g_s2p[(size_t)rowg[i]*NQ + j] = tv;
            if (tv > best) { best = tv; bk = j; }
        }
        g_sids[rowg[i]] = bk;
    }
}

// ---------------------------------------------------------------------------
// Flash: x[b,i,:] = softmax_j(q2p[i].s2p[j] - 1e4*valid[j] - 1e4*notalign) @ vv
// 8 warps x 4 rows per block; 32-key tiles; vv tile in smem.
// ---------------------------------------------------------------------------
__global__ __launch_bounds__(256) void flash_kernel(const int* __restrict__ valid)
{
    __shared__ __align__(16) float vvs[32][256];
    __shared__ float s2ps[32][NQ];
    __shared__ float q2ps[32][NQ];
    __shared__ float vmask[32];
    __shared__ int   sidss[32];
    __shared__ int   sidqs[32];
    __shared__ float ptab[NQ*NQ];
    int t = threadIdx.x, lane = t & 31, wid = t >> 5;
    int b  = blockIdx.y;
    int i0 = blockIdx.x * 32;

    for (int i = t; i < NQ*NQ; i += 256) ptab[i] = g_Ptab[i];
    for (int i = t; i < 32*NQ; i += 256) q2ps[i/NQ][i%NQ] = g_q2p[((size_t)b*NN + i0)*NQ + i];
    if (t < 32) sidqs[t] = g_sidq[b*NN + i0 + t];

    const int r0 = wid * 4;
    float m[4]  = {-INFINITY, -INFINITY, -INFINITY, -INFINITY};
    float l[4]  = {0.f, 0.f, 0.f, 0.f};
    float acc[4][8];
    #pragma unroll
    for (int r = 0; r < 4; r++)
        #pragma unroll
        for (int i = 0; i < 8; i++) acc[r][i] = 0.f;

    for (int kt = 0; kt < NN/32; kt++) {
        int k0 = kt * 32;
        __syncthreads();
        for (int i = t; i < 32*NQ; i += 256) s2ps[i/NQ][i%NQ] = g_s2p[((size_t)b*NN + k0)*NQ + i];
        if (t < 32) {
            vmask[t] = -10000.f * (float)valid[b*NN + k0 + t];
            sidss[t] = g_sids[b*NN + k0 + t];
        }
        #pragma unroll
        for (int h = 0; h < 8; h++) {
            int f4 = t + 256*h;
            int row = f4 >> 6, c4 = f4 & 63;
            *(float4*)&vvs[row][c4*4] =
                *(const float4*)(g_vv + ((size_t)b*NN + k0 + row)*CC + c4*4);
        }
        __syncthreads();

        float sc[4];
        #pragma unroll
        for (int r = 0; r < 4; r++) {
            float x = vmask[lane] + ptab[sidqs[r0+r]*NQ + sidss[lane]];
            #pragma unroll
            for (int k2 = 0; k2 < NQ; k2++) x += q2ps[r0+r][k2] * s2ps[lane][k2];
            sc[r] = x;
        }
        #pragma unroll
        for (int r = 0; r < 4; r++) {
            float mn = fmaxf(m[r], wmax(sc[r]));
            float scale = expf(m[r] - mn);
            m[r] = mn;
            float p = expf(sc[r] - mn);
            sc[r] = p;
            l[r] = l[r]*scale + wsum(p);
            #pragma unroll
            for (int i = 0; i < 8; i++) acc[r][i] *= scale;
        }
        #pragma unroll
        for (int j = 0; j < 32; j++) {
            float p0 = __shfl_sync(0xffffffffu, sc[0], j);
            float p1 = __shfl_sync(0xffffffffu, sc[1], j);
            float p2 = __shfl_sync(0xffffffffu, sc[2], j);
            float p3 = __shfl_sync(0xffffffffu, sc[3], j);
            #pragma unroll
            for (int i = 0; i < 8; i++) {
                float vvv = vvs[j][lane + 32*i];
                acc[0][i] += p0 * vvv;
                acc[1][i] += p1 * vvv;
                acc[2][i] += p2 * vvv;
                acc[3][i] += p3 * vvv;
            }
        }
    }
    #pragma unroll
    for (int r = 0; r < 4; r++) {
        float inv = 1.f / l[r];
        size_t base = ((size_t)b*NN + i0 + r0 + r)*CC;
        #pragma unroll
        for (int i = 0; i < 8; i++)
            g_xattn[base + lane + 32*i] = acc[r][i] * inv;
    }
}

// ---------------------------------------------------------------------------
// Launch
// ---------------------------------------------------------------------------
extern "C" void kernel_launch(void* const* d_in, const int* in_sizes, int n_in,
                              void* d_out, int out_size)
{
    (void)in_sizes; (void)n_in; (void)out_size;
    const float* q      = (const float*)d_in[0];
    const float* k      = (const float*)d_in[1];
    const float* v      = (const float*)d_in[2];
    const float* sv     = (const float*)d_in[3];
    const int*   svalid = (const int*)d_in[4];
    const int*   smask  = (const int*)d_in[5];
    const float* Wq     = (const float*)d_in[6];
    const float* Wk     = (const float*)d_in[7];
    const float* Wv     = (const float*)d_in[8];
    const float* Ws     = (const float*)d_in[9];
    const float* Wsq    = (const float*)d_in[10];
    const float* Wsk    = (const float*)d_in[11];
    const float* Wproj  = (const float*)d_in[12];
    const float* Wqs    = (const float*)d_in[13];
    const float* Wks    = (const float*)d_in[14];
    const float* Wvs    = (const float*)d_in[15];
    const float* Wfc    = (const float*)d_in[16];
    const float* bfc    = (const float*)d_in[17];
    const float* lng    = (const float*)d_in[18];
    const float* lnb    = (const float*)d_in[19];
    float* out = (float*)d_out;

    float *p_qs, *p_kk, *p_vv, *p_kh, *p_vh, *p_xa;
    cudaGetSymbolAddress((void**)&p_qs, g_qs);
    cudaGetSymbolAddress((void**)&p_kk, g_kk);
    cudaGetSymbolAddress((void**)&p_vv, g_vv);
    cudaGetSymbolAddress((void**)&p_kh, g_kh);
    cudaGetSymbolAddress((void**)&p_vh, g_vh);
    cudaGetSymbolAddress((void**)&p_xa, g_xattn);

    dim3 g256(2, 128), g512(4, 128);
    prep_kernel<<<1, 256>>>(smask);
    gemm_k256<<<g256, 256>>>(q, Wq, p_qs, 256);
    gemm_k256<<<g256, 256>>>(k, Wk, p_kk, 256);
    gemm_k256<<<g256, 256>>>(v, Wv, p_vv, 256);
    seed_qh_kernel<<<BB*NQ, 256>>>(sv, Ws, Wqs);
    gemm_k256<<<g512, 256>>>(p_kk, Wks, p_kh, 512);
    gemm_k256<<<g512, 256>>>(p_vv, Wvs, p_vh, 512);
    logits_kernel<<<dim3(NN/256, BB), 256>>>(smask);
    softmax_ctx_kernel<<<dim3(NQ, BB), 512>>>();
    proto_kernel<<<BB*NQ, 256>>>(Wfc, bfc, lng, lnb, Wsk, Wsq);
    rowsim_kernel<<<BB*NN/8, 256>>>(smask);
    sinkhorn_kernel<<<8, 512>>>();
    flash_kernel<<<dim3(NN/32, BB), 256>>>(svalid);
    gemm_k256<<<g256, 256>>>(p_xa, Wproj, out, 256);
}